// round 15
// baseline (speedup 1.0000x reference)
#include <cuda_runtime.h>
#include <cstdint>

typedef unsigned long long ull;

// psi[i*4096 + j] = sum_{m=0..7} Lt[i][m] * R[(i&1)*8 + m][j]
__device__ __align__(16) float gLt[4096 * 8];
__device__ __align__(32) float gR [16 * 4096];

// Per-side gate schedule (e-index -> raw gate id), layer-then-wire order.
// e bit-pairs: e0..e5:(10,11),(8,9),(6,7),(4,5),(2,3),(0,1)  e6..e10:(9,10),(7,8),(5,6),(3,4),(1,2)
//              e11..e16 = L2 (same pairs as e0..e5)          e17..e21 = L3 (same as e6..e10)
__constant__ short c_Lgi[22] = { 0, 1, 2, 3, 4, 5,  12,13,14,15,16,  23,24,25,26,27,28,  35,36,37,38,39 };
__constant__ short c_Rgi[22] = { 6, 7, 8, 9,10,11,  18,19,20,21,22,  29,30,31,32,33,34,  41,42,43,44,45 };

// Swizzle for the 32-amp-tile exchanges (bijective; banks spread for T0 in {0,4,7}).
__device__ __forceinline__ int s32(int i) { return i ^ ((i >> 5) & 31); }

// ---- packed f32x2 helpers ----
__device__ __forceinline__ ull f2pack(float a, float b) {
    ull r; asm("mov.b64 %0,{%1,%2};" : "=l"(r) : "f"(a), "f"(b)); return r;
}
__device__ __forceinline__ void f2unpack(ull x, float& a, float& b) {
    asm("mov.b64 {%0,%1},%2;" : "=f"(a), "=f"(b) : "l"(x));
}
__device__ __forceinline__ ull f2mul(ull a, ull b) {
    ull r; asm("mul.rn.f32x2 %0,%1,%2;" : "=l"(r) : "l"(a), "l"(b)); return r;
}
__device__ __forceinline__ ull f2fma(ull a, ull b, ull c) {
    ull r; asm("fma.rn.f32x2 %0,%1,%2,%3;" : "=l"(r) : "l"(a), "l"(b), "l"(c)); return r;
}

// 256-bit global accesses (sm_100+): 8 x b32 per instruction.
__device__ __forceinline__ void ldg256(const float* p, ull* a /*4 ulls out*/) {
    unsigned r0, r1, r2, r3, r4, r5, r6, r7;
    asm("ld.global.v8.b32 {%0,%1,%2,%3,%4,%5,%6,%7}, [%8];"
        : "=r"(r0), "=r"(r1), "=r"(r2), "=r"(r3),
          "=r"(r4), "=r"(r5), "=r"(r6), "=r"(r7) : "l"(p));
    asm("mov.b64 %0,{%1,%2};" : "=l"(a[0]) : "r"(r0), "r"(r1));
    asm("mov.b64 %0,{%1,%2};" : "=l"(a[1]) : "r"(r2), "r"(r3));
    asm("mov.b64 %0,{%1,%2};" : "=l"(a[2]) : "r"(r4), "r"(r5));
    asm("mov.b64 %0,{%1,%2};" : "=l"(a[3]) : "r"(r6), "r"(r7));
}
__device__ __forceinline__ void stg256(float* p, ull a0, ull a1, ull a2, ull a3) {
    unsigned r0, r1, r2, r3, r4, r5, r6, r7;
    asm("mov.b64 {%0,%1},%2;" : "=r"(r0), "=r"(r1) : "l"(a0));
    asm("mov.b64 {%0,%1},%2;" : "=r"(r2), "=r"(r3) : "l"(a1));
    asm("mov.b64 {%0,%1},%2;" : "=r"(r4), "=r"(r5) : "l"(a2));
    asm("mov.b64 {%0,%1},%2;" : "=r"(r6), "=r"(r7) : "l"(a3));
    asm volatile("st.global.v8.b32 [%0], {%1,%2,%3,%4,%5,%6,%7,%8};"
                 :: "l"(p), "r"(r0), "r"(r1), "r"(r2), "r"(r3),
                    "r"(r4), "r"(r5), "r"(r6), "r"(r7) : "memory");
}

// new[o0,o1] = sum G[i0,o0,i1,o1] old[i0,i1]; A=x00, B=i1(lower-bit) toggle,
// C=i0(higher-bit) toggle, D=both. Gate flat layout g[i0*8+o0*4+i1*2+o1].
__device__ __forceinline__ void bfly2(ull& A, ull& B, ull& C, ull& D, const ull* g) {
    ull x00 = A, x01 = B, x10 = C, x11 = D, t;
    t = f2mul(g[0], x00); t = f2fma(g[2], x01, t); t = f2fma(g[ 8], x10, t); A = f2fma(g[10], x11, t);
    t = f2mul(g[1], x00); t = f2fma(g[3], x01, t); t = f2fma(g[ 9], x10, t); B = f2fma(g[11], x11, t);
    t = f2mul(g[4], x00); t = f2fma(g[6], x01, t); t = f2fma(g[12], x10, t); C = f2fma(g[14], x11, t);
    t = f2mul(g[5], x00); t = f2fma(g[7], x01, t); t = f2fma(g[13], x10, t); D = f2fma(g[15], x11, t);
}
__device__ __forceinline__ void op1p(ull& Y0, ull& Y1, const ull* m) {
    ull y0 = Y0, y1 = Y1, t;
    t = f2mul(m[0], y0); Y0 = f2fma(m[1], y1, t);
    t = f2mul(m[2], y0); Y1 = f2fma(m[3], y1, t);
}

// Gate on packed-index bits (LO, LO+1) of a 16-element packed array.
template<int LO>
__device__ __forceinline__ void gate16p(ull* arr, const ull* g) {
#pragma unroll
    for (int hi = 0; hi < (16 >> (LO + 2)); ++hi)
#pragma unroll
        for (int lo2 = 0; lo2 < (1 << LO); ++lo2) {
            int s = (hi << (LO + 2)) | lo2;
            bfly2(arr[s], arr[s | (1 << LO)], arr[s | (2 << LO)], arr[s | (3 << LO)], g);
        }
}
// 1q on packed-index bit 3 (u-packing: tile bit 4)
__device__ __forceinline__ void op1_pb3(ull* u, const ull* m) {
#pragma unroll
    for (int k = 0; k < 8; ++k) op1p(u[k], u[k | 8], m);
}
// 1q on packed-index bit 0 (w-packing: tile bit 0)
__device__ __forceinline__ void op1_pb0(ull* w, const ull* m) {
#pragma unroll
    for (int k = 0; k < 16; k += 2) op1p(w[k], w[k + 1], m);
}

// 32-amp tile v[b4..b0]:
//  u[k] = {v[2k], v[2k+1]}  (tile bit0 packed; u-index bits = tile bits 1..4)
//  w[k] = {v[k],  v[k|16]}  (tile bit4 packed; w-index bits = tile bits 0..3)
__device__ __forceinline__ void pack32_u(const float* v, ull* u) {
#pragma unroll
    for (int k = 0; k < 16; ++k) u[k] = f2pack(v[2*k], v[2*k+1]);
}
__device__ __forceinline__ void pack32_w(const float* v, ull* w) {
#pragma unroll
    for (int k = 0; k < 16; ++k) w[k] = f2pack(v[k], v[k | 16]);
}
__device__ __forceinline__ void unpack32_u(const ull* u, float* v) {
#pragma unroll
    for (int k = 0; k < 16; ++k) f2unpack(u[k], v[2*k], v[2*k+1]);
}
__device__ __forceinline__ void w32_to_u32(const ull* w, ull* u) {
    float a[32];
#pragma unroll
    for (int k = 0; k < 16; ++k) f2unpack(w[k], a[k], a[k | 16]);
#pragma unroll
    for (int k = 0; k < 16; ++k) u[k] = f2pack(a[2*k], a[2*k+1]);
}

__device__ __forceinline__ void load_gatep(ull* gp, const ull* gsp) {
#pragma unroll
    for (int c = 0; c < 8; ++c) {
        ulonglong2 t = ((const ulonglong2*)gsp)[c];
        gp[2*c] = t.x; gp[2*c+1] = t.y;
    }
}

// Tile base for 5-bit tiles, 128 threads: spectator bits = all but T0..T0+4.
template<int T0>
__device__ __forceinline__ int tbase(int t) {
    if constexpr (T0 == 0) return t << 5;
    else return ((t >> T0) << (T0 + 5)) | (t & ((1 << T0) - 1));
}
template<int T0>
__device__ __forceinline__ void store32(float* buf, const float* v, int t) {
    const int base = tbase<T0>(t);
#pragma unroll
    for (int k = 0; k < 32; ++k) buf[s32(base + (k << T0))] = v[k];
}
template<int T0>
__device__ __forceinline__ void load32(const float* buf, float* v, int t) {
    const int base = tbase<T0>(t);
#pragma unroll
    for (int k = 0; k < 32; ++k) v[k] = buf[s32(base + (k << T0))];
}

// ============== k_smallsim: 32 blocks x 128 threads, 6 windows (R13, passing) ==============
__global__ void __launch_bounds__(128) k_smallsim(const float* __restrict__ states,
                                                  const float* __restrict__ gates)
{
    __shared__ __align__(16) float buf[2][4096];
    __shared__ __align__(16) ull gshp[352];
    __shared__ float st[24];

    const int t    = threadIdx.x;
    const int bid  = blockIdx.x;
    const int side = bid >> 4;
    const int k    = bid & 15;
    const int a    = k >> 2;
    const int b    = k & 3;

#pragma unroll
    for (int q = t; q < 352; q += 128) {
        int e = q >> 4;
        int gi = side ? c_Rgi[e] : c_Lgi[e];
        float val = gates[gi * 16 + (q & 15)];
        gshp[q] = f2pack(val, val);
    }
    if (t < 24) st[t] = states[(side ? 24 : 0) + t];

    ull mp1[4], mp2[4];
    {
        float m1[4], m2[4];
        if (side == 0) {
            m1[0]=m1[1]=m1[2]=m1[3]=0.f;  m1[(a & 1)*2 + (a >> 1)] = 1.f;   // P_a  (bit 0)
            m2[0]=m2[1]=m2[2]=m2[3]=0.f;  m2[(b & 1)*2 + (b >> 1)] = 1.f;   // P'_b (bit 0)
        } else {
            const float* g17 = gates + 17*16 + (a >> 1)*8 + (a & 1)*4;       // Q_a  (bit 11)
            m1[0]=g17[0]; m1[1]=g17[2]; m1[2]=g17[1]; m1[3]=g17[3];
            const float* g40 = gates + 40*16 + (b >> 1)*8 + (b & 1)*4;       // Q'_b (bit 11)
            m2[0]=g40[0]; m2[1]=g40[2]; m2[2]=g40[1]; m2[3]=g40[3];
        }
#pragma unroll
        for (int j = 0; j < 4; ++j) { mp1[j] = f2pack(m1[j], m1[j]); mp2[j] = f2pack(m2[j], m2[j]); }
    }
    __syncthreads();

    float v[32];
    ull u[16], w[16], gp[16], gq[16];

    {
        float pspec = 1.f;
#pragma unroll
        for (int g = 0; g < 7; ++g) pspec *= st[2*(11 - g) + ((t >> g) & 1)];
#pragma unroll
        for (int kk = 0; kk < 32; ++kk) {
            float p = pspec;
#pragma unroll
            for (int j = 0; j < 5; ++j) p *= st[2*(4 - j) + ((kk >> j) & 1)];
            v[kk] = p;
        }
    }

    // W1 (tile 7..11)
    pack32_u(v, u);
    load_gatep(gp, gshp + 0*16); load_gatep(gq, gshp + 1*16);
    gate16p<2>(u, gp);
    if (side) op1_pb3(u, mp1);
    gate16p<0>(u, gq);
    load_gatep(gp, gshp + 6*16);
    gate16p<1>(u, gp);
    unpack32_u(u, v);
    store32<7>(buf[0], v, t); __syncthreads();

    // W2 (tile 4..8)
    load32<4>(buf[0], v, t);
    pack32_w(v, w);
    load_gatep(gp, gshp + 2*16); load_gatep(gq, gshp + 3*16);
    gate16p<2>(w, gp); gate16p<0>(w, gq);
    w32_to_u32(w, u);
    load_gatep(gp, gshp + 7*16); load_gatep(gq, gshp + 8*16);
    gate16p<2>(u, gp); gate16p<0>(u, gq);
    unpack32_u(u, v);
    store32<4>(buf[1], v, t); __syncthreads();

    // W3 (tile 0..4)
    load32<0>(buf[1], v, t);
    pack32_w(v, w);
    load_gatep(gp, gshp + 4*16); load_gatep(gq, gshp + 5*16);
    gate16p<2>(w, gp); gate16p<0>(w, gq);
    if (!side) op1_pb0(w, mp1);
    w32_to_u32(w, u);
    load_gatep(gp, gshp + 9*16); load_gatep(gq, gshp + 10*16);
    gate16p<2>(u, gp); gate16p<0>(u, gq);
    unpack32_u(u, v);
    store32<0>(buf[0], v, t); __syncthreads();

    // W4 (tile 7..11)
    load32<7>(buf[0], v, t);
    pack32_u(v, u);
    load_gatep(gp, gshp + 11*16); load_gatep(gq, gshp + 12*16);
    gate16p<2>(u, gp);
    if (side) op1_pb3(u, mp2);
    gate16p<0>(u, gq);
    load_gatep(gp, gshp + 17*16);
    gate16p<1>(u, gp);
    unpack32_u(u, v);
    store32<7>(buf[1], v, t); __syncthreads();

    // W5 (tile 4..8)
    load32<4>(buf[1], v, t);
    pack32_w(v, w);
    load_gatep(gp, gshp + 13*16); load_gatep(gq, gshp + 14*16);
    gate16p<2>(w, gp); gate16p<0>(w, gq);
    w32_to_u32(w, u);
    load_gatep(gp, gshp + 18*16); load_gatep(gq, gshp + 19*16);
    gate16p<2>(u, gp); gate16p<0>(u, gq);
    unpack32_u(u, v);
    store32<4>(buf[0], v, t); __syncthreads();

    // W6 (tile 0..4)
    load32<0>(buf[0], v, t);
    pack32_w(v, w);
    load_gatep(gp, gshp + 15*16); load_gatep(gq, gshp + 16*16);
    gate16p<2>(w, gp); gate16p<0>(w, gq);
    if (!side) op1_pb0(w, mp2);
    w32_to_u32(w, u);
    load_gatep(gp, gshp + 20*16); load_gatep(gq, gshp + 21*16);
    gate16p<2>(u, gp); gate16p<0>(u, gq);
    unpack32_u(u, v);

    // Final stores: gR row = (b&1)*8 + mm is a BLOCK constant.
    const int mm = a * 2 + (b >> 1);
    const int p  = b & 1;
    if (side == 0) {
#pragma unroll
        for (int kk = 0; kk < 32; kk += 2) {
            int i = 32 * t + kk + p;
            gLt[i * 8 + mm] = v[kk + p];
        }
    } else {
        float* dst = gR + (p * 8 + mm) * 4096 + 32 * t;
#pragma unroll
        for (int kk = 0; kk < 32; ++kk) dst[kk] = v[kk];
    }
}

// ===== k_expand: 2 adjacent float4 columns/thread + 256-bit global ld/st =====
// Grid (4, 128), block 256: thread = (col 0..127, par). Thread owns floats
// [jb*1024 + 8*col, +8) of each output row; rows of parity `par` in tile ib.
__global__ void __launch_bounds__(256) k_expand(float* __restrict__ out)
{
    __shared__ __align__(16) ull sLd[32 * 8];

    const int tid = threadIdx.x;
    const int col = tid & 127;
    const int par = tid >> 7;
    const int jb  = blockIdx.x;     // 0..3
    const int ib  = blockIdx.y;     // 0..127
    const int off = jb * 1024 + 8 * col;   // float offset within a row (32B aligned)

    {   // L tile: 256 floats, duplicated packs
        float vv = gLt[ib * 256 + tid];
        sLd[tid] = f2pack(vv, vv);
    }

    // R preload: 8 rows (this parity) x 8 floats via 256-bit loads.
    ull r[8][4];
#pragma unroll
    for (int m = 0; m < 8; ++m)
        ldg256(gR + (par * 8 + m) * 4096 + off, r[m]);
    __syncthreads();

    const ulonglong2* sL2 = reinterpret_cast<const ulonglong2*>(sLd);
#pragma unroll 4
    for (int rr = 0; rr < 16; rr += 2) {
        const int r0 = 2 * rr + par;
        const int r1 = r0 + 2;
        ull A0 = 0ull, A1 = 0ull, A2 = 0ull, A3 = 0ull;   // row r0, 8 floats
        ull B0 = 0ull, B1 = 0ull, B2 = 0ull, B3 = 0ull;   // row r1, 8 floats
#pragma unroll
        for (int mq = 0; mq < 4; ++mq) {
            ulonglong2 lA = sL2[r0 * 4 + mq];
            ulonglong2 lB = sL2[r1 * 4 + mq];
            const ull* Ra = r[2*mq];
            const ull* Rb = r[2*mq + 1];
            asm("fma.rn.f32x2 %0, %1, %2, %0;" : "+l"(A0) : "l"(lA.x), "l"(Ra[0]));
            asm("fma.rn.f32x2 %0, %1, %2, %0;" : "+l"(A1) : "l"(lA.x), "l"(Ra[1]));
            asm("fma.rn.f32x2 %0, %1, %2, %0;" : "+l"(A2) : "l"(lA.x), "l"(Ra[2]));
            asm("fma.rn.f32x2 %0, %1, %2, %0;" : "+l"(A3) : "l"(lA.x), "l"(Ra[3]));
            asm("fma.rn.f32x2 %0, %1, %2, %0;" : "+l"(B0) : "l"(lB.x), "l"(Ra[0]));
            asm("fma.rn.f32x2 %0, %1, %2, %0;" : "+l"(B1) : "l"(lB.x), "l"(Ra[1]));
            asm("fma.rn.f32x2 %0, %1, %2, %0;" : "+l"(B2) : "l"(lB.x), "l"(Ra[2]));
            asm("fma.rn.f32x2 %0, %1, %2, %0;" : "+l"(B3) : "l"(lB.x), "l"(Ra[3]));
            asm("fma.rn.f32x2 %0, %1, %2, %0;" : "+l"(A0) : "l"(lA.y), "l"(Rb[0]));
            asm("fma.rn.f32x2 %0, %1, %2, %0;" : "+l"(A1) : "l"(lA.y), "l"(Rb[1]));
            asm("fma.rn.f32x2 %0, %1, %2, %0;" : "+l"(A2) : "l"(lA.y), "l"(Rb[2]));
            asm("fma.rn.f32x2 %0, %1, %2, %0;" : "+l"(A3) : "l"(lA.y), "l"(Rb[3]));
            asm("fma.rn.f32x2 %0, %1, %2, %0;" : "+l"(B0) : "l"(lB.y), "l"(Rb[0]));
            asm("fma.rn.f32x2 %0, %1, %2, %0;" : "+l"(B1) : "l"(lB.y), "l"(Rb[1]));
            asm("fma.rn.f32x2 %0, %1, %2, %0;" : "+l"(B2) : "l"(lB.y), "l"(Rb[2]));
            asm("fma.rn.f32x2 %0, %1, %2, %0;" : "+l"(B3) : "l"(lB.y), "l"(Rb[3]));
        }
        stg256(out + (ull)(ib * 32 + r0) * 4096 + off, A0, A1, A2, A3);
        stg256(out + (ull)(ib * 32 + r1) * 4096 + off, B0, B1, B2, B3);
    }
}

extern "C" void kernel_launch(void* const* d_in, const int* in_sizes, int n_in,
                              void* d_out, int out_size)
{
    const float* states = (const float*)d_in[0];   // (24, 2) f32
    const float* gates  = (const float*)d_in[1];   // (46, 2,2,2,2) f32
    (void)in_sizes; (void)n_in; (void)out_size;

    k_smallsim<<<32, 128>>>(states, gates);
    k_expand<<<dim3(4, 128), 256>>>((float*)d_out);
}

// round 16
// speedup vs baseline: 1.0508x; 1.0508x over previous
#include <cuda_runtime.h>
#include <cstdint>

typedef unsigned long long ull;

// Rank-16 factors with parity compaction:
//   psi[i*4096 + j] = sum_{m=0..7} Lt[i][m] * R[(i&1)*8 + m][j]
__device__ __align__(16) float gLt[4096 * 8];    // [i][m]
__device__ __align__(16) float gR [16 * 4096];   // [p*8+m][j]

// Gate id schedules per side, ordered by layer then wire.
// e:        0  1  2  3  4  5   6  7  8  9 10   11 12 13 14 15 16   17 18 19 20 21
// b1=10-u: 10  8  6  4  2  0   9  7  5  3  1   10  8  6  4  2  0    9  7  5  3  1
__constant__ short c_Lgi[22] = { 0, 1, 2, 3, 4, 5,  12,13,14,15,16,  23,24,25,26,27,28,  35,36,37,38,39 };
__constant__ short c_Rgi[22] = { 6, 7, 8, 9,10,11,  18,19,20,21,22,  29,30,31,32,33,34,  41,42,43,44,45 };

// Bank-conflict-killing smem swizzle: float-index bits 3,4 ^= bits 7,8.
__device__ __forceinline__ int swz(int i) { return i ^ (((i >> 7) & 3) << 3); }

// ---- packed f32x2 helpers ----
__device__ __forceinline__ ull f2pack(float a, float b) {
    ull r; asm("mov.b64 %0,{%1,%2};" : "=l"(r) : "f"(a), "f"(b)); return r;
}
__device__ __forceinline__ void f2unpack(ull x, float& a, float& b) {
    asm("mov.b64 {%0,%1},%2;" : "=f"(a), "=f"(b) : "l"(x));
}
__device__ __forceinline__ ull f2mul(ull a, ull b) {
    ull r; asm("mul.rn.f32x2 %0,%1,%2;" : "=l"(r) : "l"(a), "l"(b)); return r;
}
__device__ __forceinline__ ull f2fma(ull a, ull b, ull c) {
    ull r; asm("fma.rn.f32x2 %0,%1,%2,%3;" : "=l"(r) : "l"(a), "l"(b), "l"(c)); return r;
}

// Packed 2q butterfly: a' = g0 a + g2 b + g8 c + g10 d  (etc.)
__device__ __forceinline__ void bfly2(ull& A, ull& B, ull& C, ull& D, const ull* g) {
    ull x00 = A, x01 = B, x10 = C, x11 = D, t;
    t = f2mul(g[0], x00); t = f2fma(g[2], x01, t); t = f2fma(g[ 8], x10, t); A = f2fma(g[10], x11, t);
    t = f2mul(g[1], x00); t = f2fma(g[3], x01, t); t = f2fma(g[ 9], x10, t); B = f2fma(g[11], x11, t);
    t = f2mul(g[4], x00); t = f2fma(g[6], x01, t); t = f2fma(g[12], x10, t); C = f2fma(g[14], x11, t);
    t = f2mul(g[5], x00); t = f2fma(g[7], x01, t); t = f2fma(g[13], x10, t); D = f2fma(g[15], x11, t);
}
__device__ __forceinline__ void op1p(ull& Y0, ull& Y1, const ull* m) {
    ull y0 = Y0, y1 = Y1, t;
    t = f2mul(m[0], y0); Y0 = f2fma(m[1], y1, t);
    t = f2mul(m[2], y0); Y1 = f2fma(m[3], y1, t);
}

// Packings of the 16-amp tile v[i3 i2 i1 i0]:
//   u[k] = {v[2k], v[2k+1]}   (bit0 packed)    w[k] = {v[k], v[k|8]}   (bit3 packed)
__device__ __forceinline__ void pack_u(const float* v, ull* u) {
#pragma unroll
    for (int k = 0; k < 8; ++k) u[k] = f2pack(v[2*k], v[2*k+1]);
}
__device__ __forceinline__ void u_to_w(const ull* u, ull* w) {
    float a[16];
#pragma unroll
    for (int k = 0; k < 8; ++k) f2unpack(u[k], a[2*k], a[2*k+1]);
#pragma unroll
    for (int k = 0; k < 8; ++k) w[k] = f2pack(a[k], a[k|8]);
}
__device__ __forceinline__ void unpack_w(const ull* w, float* v) {
#pragma unroll
    for (int k = 0; k < 8; ++k) f2unpack(w[k], v[k], v[k|8]);
}

__device__ __forceinline__ void high_u(ull* u, const ull* g) {
    bfly2(u[0], u[2], u[4], u[6], g);
    bfly2(u[1], u[3], u[5], u[7], g);
}
__device__ __forceinline__ void low_w(ull* w, const ull* g) {
    bfly2(w[0], w[1], w[2], w[3], g);
    bfly2(w[4], w[5], w[6], w[7], g);
}
__device__ __forceinline__ void mid_w(ull* w, const ull* g) {
    bfly2(w[0], w[2], w[4], w[6], g);
    bfly2(w[1], w[3], w[5], w[7], g);
}
__device__ __forceinline__ void op1_b3_u(ull* u, const ull* m) {
#pragma unroll
    for (int k = 0; k < 4; ++k) op1p(u[k], u[k|4], m);
}
__device__ __forceinline__ void op1_b0_w(ull* w, const ull* m) {
#pragma unroll
    for (int k = 0; k < 8; k += 2) op1p(w[k], w[k+1], m);
}

__device__ __forceinline__ void load_gatep(ull* gp, const ull* gsp) {
#pragma unroll
    for (int c = 0; c < 8; ++c) {
        ulonglong2 t = ((const ulonglong2*)gsp)[c];
        gp[2*c] = t.x; gp[2*c+1] = t.y;
    }
}

// ---- tile exchange through swizzled smem; tile bits T0..T0+3 ----
template<int T0>
__device__ __forceinline__ void store_tile(float* sv, const float* v, int tid) {
    if constexpr (T0 == 0) {
        const int base = tid << 4;
#pragma unroll
        for (int c = 0; c < 4; ++c)
            *(float4*)&sv[swz(base + c*4)] = make_float4(v[4*c], v[4*c+1], v[4*c+2], v[4*c+3]);
    } else {
        const int base = ((tid >> T0) << (T0 + 4)) | (tid & ((1 << T0) - 1));
#pragma unroll
        for (int k = 0; k < 16; ++k) sv[swz(base + (k << T0))] = v[k];
    }
}
template<int T0>
__device__ __forceinline__ void load_tile(const float* sv, float* v, int tid) {
    if constexpr (T0 == 0) {
        const int base = tid << 4;
#pragma unroll
        for (int c = 0; c < 4; ++c) {
            float4 t = *(const float4*)&sv[swz(base + c*4)];
            v[4*c] = t.x; v[4*c+1] = t.y; v[4*c+2] = t.z; v[4*c+3] = t.w;
        }
    } else {
        const int base = ((tid >> T0) << (T0 + 4)) | (tid & ((1 << T0) - 1));
#pragma unroll
        for (int k = 0; k < 16; ++k) v[k] = sv[swz(base + (k << T0))];
    }
}

// ====== k_smallsim: R6's 256-thread / 10-window version (from the 23.008 run) ======
__global__ void __launch_bounds__(256) k_smallsim(const float* __restrict__ states,
                                                  const float* __restrict__ gates)
{
    __shared__ __align__(16) float sv[4096];
    __shared__ __align__(16) ull gshp[352];
    __shared__ float st[24];

    const int tid  = threadIdx.x;
    const int blk  = blockIdx.x;
    const int side = blk >> 4;
    const int k    = blk & 15;
    const int a    = k >> 2;
    const int b    = k & 3;

#pragma unroll
    for (int t = tid; t < 352; t += 256) {
        int e = t >> 4;
        int gi = side ? c_Rgi[e] : c_Lgi[e];
        float val = gates[gi * 16 + (t & 15)];
        gshp[t] = f2pack(val, val);
    }
    if (tid >= 232) st[tid - 232] = states[(side ? 24 : 0) + tid - 232];

    ull mp1[4], mp2[4];
    {
        float m1[4], m2[4];
        if (side == 0) {
            m1[0]=m1[1]=m1[2]=m1[3]=0.f;  m1[(a & 1)*2 + (a >> 1)] = 1.f;
            m2[0]=m2[1]=m2[2]=m2[3]=0.f;  m2[(b & 1)*2 + (b >> 1)] = 1.f;
        } else {
            const float* g17 = gates + 17*16 + (a >> 1)*8 + (a & 1)*4;
            m1[0]=g17[0]; m1[1]=g17[2]; m1[2]=g17[1]; m1[3]=g17[3];
            const float* g40 = gates + 40*16 + (b >> 1)*8 + (b & 1)*4;
            m2[0]=g40[0]; m2[1]=g40[2]; m2[2]=g40[1]; m2[3]=g40[3];
        }
#pragma unroll
        for (int j = 0; j < 4; ++j) { mp1[j] = f2pack(m1[j], m1[j]); mp2[j] = f2pack(m2[j], m2[j]); }
    }
    __syncthreads();

    float v[16];
    ull   u[8], w[8], gp[16], gq[16];

    {
        float pb = 1.f;
#pragma unroll
        for (int wv = 4; wv < 12; ++wv) pb *= st[2*wv + ((tid >> (11 - wv)) & 1)];
#pragma unroll
        for (int kk = 0; kk < 16; ++kk) {
            float p = pb;
#pragma unroll
            for (int wv = 0; wv < 4; ++wv) p *= st[2*wv + ((kk >> (3 - wv)) & 1)];
            v[kk] = p;
        }
    }

    // P1
    pack_u(v, u);
    load_gatep(gp, gshp + 0*16); load_gatep(gq, gshp + 1*16);
    high_u(u, gp);
    if (side) op1_b3_u(u, mp1);
    u_to_w(u, w); low_w(w, gq);
    unpack_w(w, v);
    store_tile<8>(sv, v, tid); __syncthreads();
    // P2
    load_tile<4>(sv, v, tid);  pack_u(v, u);
    load_gatep(gp, gshp + 2*16); load_gatep(gq, gshp + 3*16);
    high_u(u, gp); u_to_w(u, w); low_w(w, gq);
    unpack_w(w, v); store_tile<4>(sv, v, tid); __syncthreads();
    // P3
    load_tile<0>(sv, v, tid);  pack_u(v, u);
    load_gatep(gp, gshp + 4*16); load_gatep(gq, gshp + 5*16);
    high_u(u, gp); u_to_w(u, w); low_w(w, gq);
    load_gatep(gp, gshp + 10*16); mid_w(w, gp);
    if (!side) op1_b0_w(w, mp1);
    unpack_w(w, v); store_tile<0>(sv, v, tid); __syncthreads();
    // P4
    load_tile<7>(sv, v, tid);  pack_u(v, u);
    load_gatep(gp, gshp + 6*16); load_gatep(gq, gshp + 7*16);
    high_u(u, gp); u_to_w(u, w); low_w(w, gq);
    unpack_w(w, v); store_tile<7>(sv, v, tid); __syncthreads();
    // P5
    load_tile<3>(sv, v, tid);  pack_u(v, u);
    load_gatep(gp, gshp + 8*16); load_gatep(gq, gshp + 9*16);
    high_u(u, gp); u_to_w(u, w); low_w(w, gq);
    unpack_w(w, v); store_tile<3>(sv, v, tid); __syncthreads();
    // P6
    load_tile<8>(sv, v, tid);  pack_u(v, u);
    load_gatep(gp, gshp + 11*16); load_gatep(gq, gshp + 12*16);
    high_u(u, gp);
    if (side) op1_b3_u(u, mp2);
    u_to_w(u, w); low_w(w, gq);
    unpack_w(w, v); store_tile<8>(sv, v, tid); __syncthreads();
    // P7
    load_tile<4>(sv, v, tid);  pack_u(v, u);
    load_gatep(gp, gshp + 13*16); load_gatep(gq, gshp + 14*16);
    high_u(u, gp); u_to_w(u, w); low_w(w, gq);
    unpack_w(w, v); store_tile<4>(sv, v, tid); __syncthreads();
    // P8
    load_tile<0>(sv, v, tid);  pack_u(v, u);
    load_gatep(gp, gshp + 15*16); load_gatep(gq, gshp + 16*16);
    high_u(u, gp); u_to_w(u, w); low_w(w, gq);
    load_gatep(gp, gshp + 21*16); mid_w(w, gp);
    if (!side) op1_b0_w(w, mp2);
    unpack_w(w, v); store_tile<0>(sv, v, tid); __syncthreads();
    // P9
    load_tile<7>(sv, v, tid);  pack_u(v, u);
    load_gatep(gp, gshp + 17*16); load_gatep(gq, gshp + 18*16);
    high_u(u, gp); u_to_w(u, w); low_w(w, gq);
    unpack_w(w, v); store_tile<7>(sv, v, tid); __syncthreads();
    // P10
    load_tile<3>(sv, v, tid);  pack_u(v, u);
    load_gatep(gp, gshp + 19*16); load_gatep(gq, gshp + 20*16);
    high_u(u, gp); u_to_w(u, w); low_w(w, gq);
    unpack_w(w, v); store_tile<3>(sv, v, tid); __syncthreads();

    const int mm = a * 2 + (b >> 1);
    const int p  = b & 1;
    if (side == 0) {
#pragma unroll
        for (int t = tid; t < 2048; t += 256) {
            int i = 2 * t + p;
            gLt[i * 8 + mm] = sv[swz(i)];
        }
    } else {
#pragma unroll
        for (int j = tid; j < 4096; j += 256)
            gR[(p * 8 + mm) * 4096 + j] = sv[swz(j)];
    }
}

// ====== k_expand: R11/R13's measured-best (13.38 µs), byte-identical ======
__global__ void __launch_bounds__(256) k_expand(float4* __restrict__ out)
{
    __shared__ __align__(16) ull sLd[32 * 8];

    const int tid = threadIdx.x;
    const int col = tid & 127;
    const int par = tid >> 7;
    const int jb  = blockIdx.x;
    const int ib  = blockIdx.y;

    {
        float vv = gLt[ib * 256 + tid];
        sLd[tid] = f2pack(vv, vv);
    }
    const float4* gR4 = reinterpret_cast<const float4*>(gR);
    const int jq = jb * 128 + col;
    ull rlo[8], rhi[8];
#pragma unroll
    for (int m = 0; m < 8; ++m) {
        float4 r = gR4[(par * 8 + m) * 1024 + jq];
        rlo[m] = f2pack(r.x, r.y);
        rhi[m] = f2pack(r.z, r.w);
    }
    __syncthreads();

    const ulonglong2* sL2 = reinterpret_cast<const ulonglong2*>(sLd);
#pragma unroll 4
    for (int rr = 0; rr < 16; rr += 2) {
        const int r0 = 2 * rr + par;
        const int r1 = r0 + 2;
        ull a0 = 0ull, a1 = 0ull, b0 = 0ull, b1 = 0ull;
#pragma unroll
        for (int mq = 0; mq < 4; ++mq) {
            ulonglong2 lA = sL2[r0 * 4 + mq];
            ulonglong2 lB = sL2[r1 * 4 + mq];
            asm("fma.rn.f32x2 %0, %1, %2, %0;" : "+l"(a0) : "l"(lA.x), "l"(rlo[2*mq]));
            asm("fma.rn.f32x2 %0, %1, %2, %0;" : "+l"(a1) : "l"(lA.x), "l"(rhi[2*mq]));
            asm("fma.rn.f32x2 %0, %1, %2, %0;" : "+l"(b0) : "l"(lB.x), "l"(rlo[2*mq]));
            asm("fma.rn.f32x2 %0, %1, %2, %0;" : "+l"(b1) : "l"(lB.x), "l"(rhi[2*mq]));
            asm("fma.rn.f32x2 %0, %1, %2, %0;" : "+l"(a0) : "l"(lA.y), "l"(rlo[2*mq+1]));
            asm("fma.rn.f32x2 %0, %1, %2, %0;" : "+l"(a1) : "l"(lA.y), "l"(rhi[2*mq+1]));
            asm("fma.rn.f32x2 %0, %1, %2, %0;" : "+l"(b0) : "l"(lB.y), "l"(rlo[2*mq+1]));
            asm("fma.rn.f32x2 %0, %1, %2, %0;" : "+l"(b1) : "l"(lB.y), "l"(rhi[2*mq+1]));
        }
        float e0, e1, e2, e3, f0, f1, f2, f3;
        f2unpack(a0, e0, e1); f2unpack(a1, e2, e3);
        f2unpack(b0, f0, f1); f2unpack(b1, f2, f3);
        out[(ib * 32 + r0) * 1024 + jq] = make_float4(e0, e1, e2, e3);
        out[(ib * 32 + r1) * 1024 + jq] = make_float4(f0, f1, f2, f3);
    }
}

extern "C" void kernel_launch(void* const* d_in, const int* in_sizes, int n_in,
                              void* d_out, int out_size)
{
    const float* states = (const float*)d_in[0];   // (24, 2) f32
    const float* gates  = (const float*)d_in[1];   // (46, 2,2,2,2) f32
    (void)in_sizes; (void)n_in; (void)out_size;

    k_smallsim<<<32, 256>>>(states, gates);
    k_expand<<<dim3(8, 128), 256>>>((float4*)d_out);
}

// round 17
// speedup vs baseline: 1.0640x; 1.0125x over previous
#include <cuda_runtime.h>
#include <cstdint>

typedef unsigned long long ull;

// Rank-16 factors with parity compaction:
//   psi[i*4096 + j] = sum_{m=0..7} Lt[i][m] * R[(i&1)*8 + m][j]
__device__ __align__(16) float gLt[4096 * 8];    // [i][m]
__device__ __align__(16) float gR [16 * 4096];   // [p*8+m][j]

// Gate id schedules per side, ordered by layer then wire.
// e:        0  1  2  3  4  5   6  7  8  9 10   11 12 13 14 15 16   17 18 19 20 21
// b1=10-u: 10  8  6  4  2  0   9  7  5  3  1   10  8  6  4  2  0    9  7  5  3  1
__constant__ short c_Lgi[22] = { 0, 1, 2, 3, 4, 5,  12,13,14,15,16,  23,24,25,26,27,28,  35,36,37,38,39 };
__constant__ short c_Rgi[22] = { 6, 7, 8, 9,10,11,  18,19,20,21,22,  29,30,31,32,33,34,  41,42,43,44,45 };

// Bank-conflict-killing smem swizzle: float-index bits 3,4 ^= bits 7,8.
__device__ __forceinline__ int swz(int i) { return i ^ (((i >> 7) & 3) << 3); }

// ---- packed f32x2 helpers ----
__device__ __forceinline__ ull f2pack(float a, float b) {
    ull r; asm("mov.b64 %0,{%1,%2};" : "=l"(r) : "f"(a), "f"(b)); return r;
}
__device__ __forceinline__ void f2unpack(ull x, float& a, float& b) {
    asm("mov.b64 {%0,%1},%2;" : "=f"(a), "=f"(b) : "l"(x));
}
__device__ __forceinline__ ull f2mul(ull a, ull b) {
    ull r; asm("mul.rn.f32x2 %0,%1,%2;" : "=l"(r) : "l"(a), "l"(b)); return r;
}
__device__ __forceinline__ ull f2fma(ull a, ull b, ull c) {
    ull r; asm("fma.rn.f32x2 %0,%1,%2,%3;" : "=l"(r) : "l"(a), "l"(b), "l"(c)); return r;
}

// Packed 2q butterfly: a' = g0 a + g2 b + g8 c + g10 d  (etc.)
__device__ __forceinline__ void bfly2(ull& A, ull& B, ull& C, ull& D, const ull* g) {
    ull x00 = A, x01 = B, x10 = C, x11 = D, t;
    t = f2mul(g[0], x00); t = f2fma(g[2], x01, t); t = f2fma(g[ 8], x10, t); A = f2fma(g[10], x11, t);
    t = f2mul(g[1], x00); t = f2fma(g[3], x01, t); t = f2fma(g[ 9], x10, t); B = f2fma(g[11], x11, t);
    t = f2mul(g[4], x00); t = f2fma(g[6], x01, t); t = f2fma(g[12], x10, t); C = f2fma(g[14], x11, t);
    t = f2mul(g[5], x00); t = f2fma(g[7], x01, t); t = f2fma(g[13], x10, t); D = f2fma(g[15], x11, t);
}
__device__ __forceinline__ void op1p(ull& Y0, ull& Y1, const ull* m) {
    ull y0 = Y0, y1 = Y1, t;
    t = f2mul(m[0], y0); Y0 = f2fma(m[1], y1, t);
    t = f2mul(m[2], y0); Y1 = f2fma(m[3], y1, t);
}

// Packings of the 16-amp tile v[i3 i2 i1 i0]:
//   u[k] = {v[2k], v[2k+1]}   (bit0 packed)    w[k] = {v[k], v[k|8]}   (bit3 packed)
__device__ __forceinline__ void pack_u(const float* v, ull* u) {
#pragma unroll
    for (int k = 0; k < 8; ++k) u[k] = f2pack(v[2*k], v[2*k+1]);
}
__device__ __forceinline__ void u_to_w(const ull* u, ull* w) {
    float a[16];
#pragma unroll
    for (int k = 0; k < 8; ++k) f2unpack(u[k], a[2*k], a[2*k+1]);
#pragma unroll
    for (int k = 0; k < 8; ++k) w[k] = f2pack(a[k], a[k|8]);
}
__device__ __forceinline__ void unpack_w(const ull* w, float* v) {
#pragma unroll
    for (int k = 0; k < 8; ++k) f2unpack(w[k], v[k], v[k|8]);
}

__device__ __forceinline__ void high_u(ull* u, const ull* g) {
    bfly2(u[0], u[2], u[4], u[6], g);
    bfly2(u[1], u[3], u[5], u[7], g);
}
__device__ __forceinline__ void low_w(ull* w, const ull* g) {
    bfly2(w[0], w[1], w[2], w[3], g);
    bfly2(w[4], w[5], w[6], w[7], g);
}
__device__ __forceinline__ void mid_w(ull* w, const ull* g) {
    bfly2(w[0], w[2], w[4], w[6], g);
    bfly2(w[1], w[3], w[5], w[7], g);
}
__device__ __forceinline__ void op1_b3_u(ull* u, const ull* m) {
#pragma unroll
    for (int k = 0; k < 4; ++k) op1p(u[k], u[k|4], m);
}
__device__ __forceinline__ void op1_b0_w(ull* w, const ull* m) {
#pragma unroll
    for (int k = 0; k < 8; k += 2) op1p(w[k], w[k+1], m);
}

__device__ __forceinline__ void load_gatep(ull* gp, const ull* gsp) {
#pragma unroll
    for (int c = 0; c < 8; ++c) {
        ulonglong2 t = ((const ulonglong2*)gsp)[c];
        gp[2*c] = t.x; gp[2*c+1] = t.y;
    }
}

// ---- tile exchange through swizzled smem; tile bits T0..T0+3 ----
template<int T0>
__device__ __forceinline__ void store_tile(float* sv, const float* v, int tid) {
    if constexpr (T0 == 0) {
        const int base = tid << 4;
#pragma unroll
        for (int c = 0; c < 4; ++c)
            *(float4*)&sv[swz(base + c*4)] = make_float4(v[4*c], v[4*c+1], v[4*c+2], v[4*c+3]);
    } else {
        const int base = ((tid >> T0) << (T0 + 4)) | (tid & ((1 << T0) - 1));
#pragma unroll
        for (int k = 0; k < 16; ++k) sv[swz(base + (k << T0))] = v[k];
    }
}
template<int T0>
__device__ __forceinline__ void load_tile(const float* sv, float* v, int tid) {
    if constexpr (T0 == 0) {
        const int base = tid << 4;
#pragma unroll
        for (int c = 0; c < 4; ++c) {
            float4 t = *(const float4*)&sv[swz(base + c*4)];
            v[4*c] = t.x; v[4*c+1] = t.y; v[4*c+2] = t.z; v[4*c+3] = t.w;
        }
    } else {
        const int base = ((tid >> T0) << (T0 + 4)) | (tid & ((1 << T0) - 1));
#pragma unroll
        for (int k = 0; k < 16; ++k) v[k] = sv[swz(base + (k << T0))];
    }
}

// ====== k_smallsim: R6's 256-thread / 10-window version (from the 23.008 run) ======
__global__ void __launch_bounds__(256) k_smallsim(const float* __restrict__ states,
                                                  const float* __restrict__ gates)
{
    __shared__ __align__(16) float sv[4096];
    __shared__ __align__(16) ull gshp[352];
    __shared__ float st[24];

    const int tid  = threadIdx.x;
    const int blk  = blockIdx.x;
    const int side = blk >> 4;
    const int k    = blk & 15;
    const int a    = k >> 2;
    const int b    = k & 3;

#pragma unroll
    for (int t = tid; t < 352; t += 256) {
        int e = t >> 4;
        int gi = side ? c_Rgi[e] : c_Lgi[e];
        float val = gates[gi * 16 + (t & 15)];
        gshp[t] = f2pack(val, val);
    }
    if (tid >= 232) st[tid - 232] = states[(side ? 24 : 0) + tid - 232];

    ull mp1[4], mp2[4];
    {
        float m1[4], m2[4];
        if (side == 0) {
            m1[0]=m1[1]=m1[2]=m1[3]=0.f;  m1[(a & 1)*2 + (a >> 1)] = 1.f;
            m2[0]=m2[1]=m2[2]=m2[3]=0.f;  m2[(b & 1)*2 + (b >> 1)] = 1.f;
        } else {
            const float* g17 = gates + 17*16 + (a >> 1)*8 + (a & 1)*4;
            m1[0]=g17[0]; m1[1]=g17[2]; m1[2]=g17[1]; m1[3]=g17[3];
            const float* g40 = gates + 40*16 + (b >> 1)*8 + (b & 1)*4;
            m2[0]=g40[0]; m2[1]=g40[2]; m2[2]=g40[1]; m2[3]=g40[3];
        }
#pragma unroll
        for (int j = 0; j < 4; ++j) { mp1[j] = f2pack(m1[j], m1[j]); mp2[j] = f2pack(m2[j], m2[j]); }
    }
    __syncthreads();

    float v[16];
    ull   u[8], w[8], gp[16], gq[16];

    {
        float pb = 1.f;
#pragma unroll
        for (int wv = 4; wv < 12; ++wv) pb *= st[2*wv + ((tid >> (11 - wv)) & 1)];
#pragma unroll
        for (int kk = 0; kk < 16; ++kk) {
            float p = pb;
#pragma unroll
            for (int wv = 0; wv < 4; ++wv) p *= st[2*wv + ((kk >> (3 - wv)) & 1)];
            v[kk] = p;
        }
    }

    // P1
    pack_u(v, u);
    load_gatep(gp, gshp + 0*16); load_gatep(gq, gshp + 1*16);
    high_u(u, gp);
    if (side) op1_b3_u(u, mp1);
    u_to_w(u, w); low_w(w, gq);
    unpack_w(w, v);
    store_tile<8>(sv, v, tid); __syncthreads();
    // P2
    load_tile<4>(sv, v, tid);  pack_u(v, u);
    load_gatep(gp, gshp + 2*16); load_gatep(gq, gshp + 3*16);
    high_u(u, gp); u_to_w(u, w); low_w(w, gq);
    unpack_w(w, v); store_tile<4>(sv, v, tid); __syncthreads();
    // P3
    load_tile<0>(sv, v, tid);  pack_u(v, u);
    load_gatep(gp, gshp + 4*16); load_gatep(gq, gshp + 5*16);
    high_u(u, gp); u_to_w(u, w); low_w(w, gq);
    load_gatep(gp, gshp + 10*16); mid_w(w, gp);
    if (!side) op1_b0_w(w, mp1);
    unpack_w(w, v); store_tile<0>(sv, v, tid); __syncthreads();
    // P4
    load_tile<7>(sv, v, tid);  pack_u(v, u);
    load_gatep(gp, gshp + 6*16); load_gatep(gq, gshp + 7*16);
    high_u(u, gp); u_to_w(u, w); low_w(w, gq);
    unpack_w(w, v); store_tile<7>(sv, v, tid); __syncthreads();
    // P5
    load_tile<3>(sv, v, tid);  pack_u(v, u);
    load_gatep(gp, gshp + 8*16); load_gatep(gq, gshp + 9*16);
    high_u(u, gp); u_to_w(u, w); low_w(w, gq);
    unpack_w(w, v); store_tile<3>(sv, v, tid); __syncthreads();
    // P6
    load_tile<8>(sv, v, tid);  pack_u(v, u);
    load_gatep(gp, gshp + 11*16); load_gatep(gq, gshp + 12*16);
    high_u(u, gp);
    if (side) op1_b3_u(u, mp2);
    u_to_w(u, w); low_w(w, gq);
    unpack_w(w, v); store_tile<8>(sv, v, tid); __syncthreads();
    // P7
    load_tile<4>(sv, v, tid);  pack_u(v, u);
    load_gatep(gp, gshp + 13*16); load_gatep(gq, gshp + 14*16);
    high_u(u, gp); u_to_w(u, w); low_w(w, gq);
    unpack_w(w, v); store_tile<4>(sv, v, tid); __syncthreads();
    // P8
    load_tile<0>(sv, v, tid);  pack_u(v, u);
    load_gatep(gp, gshp + 15*16); load_gatep(gq, gshp + 16*16);
    high_u(u, gp); u_to_w(u, w); low_w(w, gq);
    load_gatep(gp, gshp + 21*16); mid_w(w, gp);
    if (!side) op1_b0_w(w, mp2);
    unpack_w(w, v); store_tile<0>(sv, v, tid); __syncthreads();
    // P9
    load_tile<7>(sv, v, tid);  pack_u(v, u);
    load_gatep(gp, gshp + 17*16); load_gatep(gq, gshp + 18*16);
    high_u(u, gp); u_to_w(u, w); low_w(w, gq);
    unpack_w(w, v); store_tile<7>(sv, v, tid); __syncthreads();
    // P10
    load_tile<3>(sv, v, tid);  pack_u(v, u);
    load_gatep(gp, gshp + 19*16); load_gatep(gq, gshp + 20*16);
    high_u(u, gp); u_to_w(u, w); low_w(w, gq);
    unpack_w(w, v); store_tile<3>(sv, v, tid); __syncthreads();

    const int mm = a * 2 + (b >> 1);
    const int p  = b & 1;
    if (side == 0) {
#pragma unroll
        for (int t = tid; t < 2048; t += 256) {
            int i = 2 * t + p;
            gLt[i * 8 + mm] = sv[swz(i)];
        }
    } else {
#pragma unroll
        for (int j = tid; j < 4096; j += 256)
            gR[(p * 8 + mm) * 4096 + j] = sv[swz(j)];
    }
}

// ====== k_expand: R11/R13's measured-best (13.38 µs), byte-identical ======
__global__ void __launch_bounds__(256) k_expand(float4* __restrict__ out)
{
    __shared__ __align__(16) ull sLd[32 * 8];

    const int tid = threadIdx.x;
    const int col = tid & 127;
    const int par = tid >> 7;
    const int jb  = blockIdx.x;
    const int ib  = blockIdx.y;

    {
        float vv = gLt[ib * 256 + tid];
        sLd[tid] = f2pack(vv, vv);
    }
    const float4* gR4 = reinterpret_cast<const float4*>(gR);
    const int jq = jb * 128 + col;
    ull rlo[8], rhi[8];
#pragma unroll
    for (int m = 0; m < 8; ++m) {
        float4 r = gR4[(par * 8 + m) * 1024 + jq];
        rlo[m] = f2pack(r.x, r.y);
        rhi[m] = f2pack(r.z, r.w);
    }
    __syncthreads();

    const ulonglong2* sL2 = reinterpret_cast<const ulonglong2*>(sLd);
#pragma unroll 4
    for (int rr = 0; rr < 16; rr += 2) {
        const int r0 = 2 * rr + par;
        const int r1 = r0 + 2;
        ull a0 = 0ull, a1 = 0ull, b0 = 0ull, b1 = 0ull;
#pragma unroll
        for (int mq = 0; mq < 4; ++mq) {
            ulonglong2 lA = sL2[r0 * 4 + mq];
            ulonglong2 lB = sL2[r1 * 4 + mq];
            asm("fma.rn.f32x2 %0, %1, %2, %0;" : "+l"(a0) : "l"(lA.x), "l"(rlo[2*mq]));
            asm("fma.rn.f32x2 %0, %1, %2, %0;" : "+l"(a1) : "l"(lA.x), "l"(rhi[2*mq]));
            asm("fma.rn.f32x2 %0, %1, %2, %0;" : "+l"(b0) : "l"(lB.x), "l"(rlo[2*mq]));
            asm("fma.rn.f32x2 %0, %1, %2, %0;" : "+l"(b1) : "l"(lB.x), "l"(rhi[2*mq]));
            asm("fma.rn.f32x2 %0, %1, %2, %0;" : "+l"(a0) : "l"(lA.y), "l"(rlo[2*mq+1]));
            asm("fma.rn.f32x2 %0, %1, %2, %0;" : "+l"(a1) : "l"(lA.y), "l"(rhi[2*mq+1]));
            asm("fma.rn.f32x2 %0, %1, %2, %0;" : "+l"(b0) : "l"(lB.y), "l"(rlo[2*mq+1]));
            asm("fma.rn.f32x2 %0, %1, %2, %0;" : "+l"(b1) : "l"(lB.y), "l"(rhi[2*mq+1]));
        }
        float e0, e1, e2, e3, f0, f1, f2, f3;
        f2unpack(a0, e0, e1); f2unpack(a1, e2, e3);
        f2unpack(b0, f0, f1); f2unpack(b1, f2, f3);
        out[(ib * 32 + r0) * 1024 + jq] = make_float4(e0, e1, e2, e3);
        out[(ib * 32 + r1) * 1024 + jq] = make_float4(f0, f1, f2, f3);
    }
}

extern "C" void kernel_launch(void* const* d_in, const int* in_sizes, int n_in,
                              void* d_out, int out_size)
{
    const float* states = (const float*)d_in[0];   // (24, 2) f32
    const float* gates  = (const float*)d_in[1];   // (46, 2,2,2,2) f32
    (void)in_sizes; (void)n_in; (void)out_size;

    k_smallsim<<<32, 256>>>(states, gates);
    k_expand<<<dim3(8, 128), 256>>>((float4*)d_out);
}